// round 2
// baseline (speedup 1.0000x reference)
#include <cuda_runtime.h>
#include <math.h>
#include <stdint.h>

// ---------------- problem constants (fixed shapes) ----------------
#define B_   8
#define T_   1024
#define C_   768
#define H_   12
#define HS_  64
#define PH_  32
#define PW_  32
#define NR_  (B_ * T_)          // 8192 rows
#define NC_  ((size_t)NR_ * C_) // 6291456 elems

// ---------------- scratch layout (single __device__ array) ----------------
// 14 full [NR_,C_] buffers + t5(160) + h1(64) + ruk(H)
__device__ __align__(16) float g_scratch[14 * NC_ + (size_t)NR_ * 160 + (size_t)NR_ * 64 + (size_t)NR_ * H_];

#define OFF_XX   ((size_t)0)
#define OFF_XXX  (OFF_XX  + NC_)
#define OFF_T5   (OFF_XXX + NC_)
#define OFF_XW   (OFF_T5  + (size_t)NR_ * 160)
#define OFF_XK   (OFF_XW  + NC_)
#define OFF_XV   (OFF_XK  + NC_)
#define OFF_XR   (OFF_XV  + NC_)
#define OFF_XG   (OFF_XR  + NC_)
#define OFF_R    (OFF_XG  + NC_)
#define OFF_K    (OFF_R   + NC_)
#define OFF_V    (OFF_K   + NC_)
#define OFF_G    (OFF_V   + NC_)
#define OFF_H1   (OFF_G   + NC_)
#define OFF_WDEC (OFF_H1  + (size_t)NR_ * 64)
#define OFF_Y    (OFF_WDEC+ NC_)
#define OFF_YN   (OFF_Y   + NC_)
#define OFF_RUK  (OFF_YN  + NC_)
// end = OFF_RUK + NR_*H_  ==  14*NC_ + NR_*160 + NR_*64 + NR_*H_   (matches size)

// ==========================================================================
// Kernel 1: q-shift  ->  xx = shift(x) - x ;  xxx = x + xx * maa_x
// ==========================================================================
__global__ void k_shift(const float* __restrict__ x, const float* __restrict__ maa_x,
                        float* __restrict__ xx, float* __restrict__ xxx)
{
    int idx = blockIdx.x * blockDim.x + threadIdx.x;   // < NR_*C_
    int c  = idx % C_;
    int bt = idx / C_;
    int t  = bt % T_;
    int w  = t % PW_;
    int h  = t / PW_;
    int quarter = (c & (HS_ - 1)) >> 4;                // head_dim/4 = 16

    float src = 0.f;
    if (quarter == 0)      { if (w > 0)       src = x[idx - C_]; }
    else if (quarter == 1) { if (w < PW_ - 1) src = x[idx + C_]; }
    else if (quarter == 2) { if (h > 0)       src = x[idx - PW_ * C_]; }
    else                   { if (h < PH_ - 1) src = x[idx + PW_ * C_]; }

    float xv = x[idx];
    float d  = src - xv;
    xx[idx]  = d;
    xxx[idx] = fmaf(d, maa_x[c], xv);
}

// ==========================================================================
// Generic tiled fp32 GEMM:  C[M,N] = epi( A[M,K] @ B )
//   BNT = true : B stored [N,K] row-major (computes A @ B^T)
//   BNT = false: B stored [K,N] row-major (computes A @ B)
// EPI: 0 none, 1 tanh, 2 relu, 3 exp(-exp(bias[n] + v))
// ==========================================================================
template<int EPI, bool BNT>
__global__ void __launch_bounds__(256)
k_gemm(const float* __restrict__ A, const float* __restrict__ B,
       float* __restrict__ Cmat, int M, int N, int K, const float* __restrict__ bias)
{
    __shared__ float As[16][132];
    __shared__ float Bs[16][132];

    const int m0  = blockIdx.y * 128;
    const int n0  = blockIdx.x * 128;
    const int tid = threadIdx.x;
    const int tm  = tid >> 4;     // 0..15
    const int tn  = tid & 15;     // 0..15

    float acc[8][8];
#pragma unroll
    for (int i = 0; i < 8; i++)
#pragma unroll
        for (int j = 0; j < 8; j++) acc[i][j] = 0.f;

    for (int k0 = 0; k0 < K; k0 += 16) {
        // ---- load A tile 128x16 (transpose into As[k][m]) ----
#pragma unroll
        for (int l = 0; l < 2; l++) {
            int e  = tid + l * 256;           // float4 id 0..511
            int am = e >> 2;                  // 0..127
            int ak = (e & 3) * 4;             // 0,4,8,12
            float4 a4 = *(const float4*)(A + (size_t)(m0 + am) * K + k0 + ak);
            As[ak + 0][am] = a4.x; As[ak + 1][am] = a4.y;
            As[ak + 2][am] = a4.z; As[ak + 3][am] = a4.w;
        }
        // ---- load B tile ----
        if (BNT) {
#pragma unroll
            for (int l = 0; l < 2; l++) {
                int e  = tid + l * 256;
                int bn = e >> 2;
                int bk = (e & 3) * 4;
                float4 b4 = make_float4(0.f, 0.f, 0.f, 0.f);
                if (n0 + bn < N)
                    b4 = *(const float4*)(B + (size_t)(n0 + bn) * K + k0 + bk);
                Bs[bk + 0][bn] = b4.x; Bs[bk + 1][bn] = b4.y;
                Bs[bk + 2][bn] = b4.z; Bs[bk + 3][bn] = b4.w;
            }
        } else {
#pragma unroll
            for (int l = 0; l < 2; l++) {
                int e  = tid + l * 256;
                int bk = e >> 5;              // 0..15
                int bn = (e & 31) * 4;        // 0..124
                float4 b4 = make_float4(0.f, 0.f, 0.f, 0.f);
                if (n0 + bn < N)
                    b4 = *(const float4*)(B + (size_t)(k0 + bk) * N + n0 + bn);
                *(float4*)(&Bs[bk][bn]) = b4;
            }
        }
        __syncthreads();

#pragma unroll
        for (int kk = 0; kk < 16; kk++) {
            float a[8], b[8];
            *(float4*)(a)     = *(const float4*)(&As[kk][tm * 8]);
            *(float4*)(a + 4) = *(const float4*)(&As[kk][tm * 8 + 4]);
            *(float4*)(b)     = *(const float4*)(&Bs[kk][tn * 8]);
            *(float4*)(b + 4) = *(const float4*)(&Bs[kk][tn * 8 + 4]);
#pragma unroll
            for (int i = 0; i < 8; i++)
#pragma unroll
                for (int j = 0; j < 8; j++)
                    acc[i][j] = fmaf(a[i], b[j], acc[i][j]);
        }
        __syncthreads();
    }

    // ---- epilogue + store ----
#pragma unroll
    for (int i = 0; i < 8; i++) {
        int m = m0 + tm * 8 + i;
#pragma unroll
        for (int j = 0; j < 8; j++) {
            int n = n0 + tn * 8 + j;
            if (n < N) {
                float v = acc[i][j];
                if (EPI == 1) v = tanhf(v);
                else if (EPI == 2) v = fmaxf(v, 0.f);
                else if (EPI == 3) v = expf(-expf(bias[n] + v));
                Cmat[(size_t)m * N + n] = v;
            }
        }
    }
}

// ==========================================================================
// Kernel 3: token-mix  x{w,k,v,r,g} = x + xx*(maa_f + (t5 @ maa_w2[f]))
// ==========================================================================
__global__ void __launch_bounds__(256)
k_mix(const float* __restrict__ x, const float* __restrict__ xx,
      const float* __restrict__ t5, const float* __restrict__ w2,
      const float* __restrict__ ma0, const float* __restrict__ ma1,
      const float* __restrict__ ma2, const float* __restrict__ ma3,
      const float* __restrict__ ma4,
      float* __restrict__ o0, float* __restrict__ o1, float* __restrict__ o2,
      float* __restrict__ o3, float* __restrict__ o4)
{
    const int r0  = blockIdx.x * 32;
    const int c0  = blockIdx.y * 128;
    const int tid = threadIdx.x;
    const int cl  = tid & 127;   // column in tile
    const int rh  = tid >> 7;    // 0/1 row phase

    __shared__ __align__(16) float tsh[32][36];   // [row][r]
    __shared__ float wsh[32][128];                // [r][col]

    const float* maas[5] = { ma0, ma1, ma2, ma3, ma4 };
    float*       outs[5] = { o0, o1, o2, o3, o4 };

    float xr_[16], xxr_[16];
#pragma unroll
    for (int kk = 0; kk < 16; kk++) {
        size_t idx = (size_t)(r0 + rh + 2 * kk) * C_ + c0 + cl;
        xr_[kk]  = x[idx];
        xxr_[kk] = xx[idx];
    }

#pragma unroll
    for (int f = 0; f < 5; f++) {
#pragma unroll
        for (int l = 0; l < 4; l++) {
            int e = tid + l * 256;               // 0..1023
            tsh[e >> 5][e & 31] = t5[(size_t)(r0 + (e >> 5)) * 160 + f * 32 + (e & 31)];
        }
#pragma unroll
        for (int l = 0; l < 16; l++) {
            int e = tid + l * 256;               // 0..4095
            wsh[e >> 7][e & 127] = w2[(size_t)(f * 32 + (e >> 7)) * C_ + c0 + (e & 127)];
        }
        __syncthreads();

        float wreg[32];
#pragma unroll
        for (int rr = 0; rr < 32; rr++) wreg[rr] = wsh[rr][cl];

        const float mf = maas[f][c0 + cl];
        float* const outp = outs[f];
#pragma unroll
        for (int kk = 0; kk < 16; kk++) {
            const int row = rh + 2 * kk;
            const float4* trow = (const float4*)(&tsh[row][0]);
            float a = 0.f;
#pragma unroll
            for (int q = 0; q < 8; q++) {
                float4 t4 = trow[q];
                a = fmaf(t4.x, wreg[4 * q + 0], a);
                a = fmaf(t4.y, wreg[4 * q + 1], a);
                a = fmaf(t4.z, wreg[4 * q + 2], a);
                a = fmaf(t4.w, wreg[4 * q + 3], a);
            }
            size_t idx = (size_t)(r0 + row) * C_ + c0 + cl;
            outp[idx] = fmaf(xxr_[kk], mf + a, xr_[kk]);
        }
        __syncthreads();
    }
}

// ==========================================================================
// Kernel: ruk[row,h] = sum_j r[row, h*64+j] * u[h*64+j] * k[row, h*64+j]
// ==========================================================================
__global__ void k_ruk(const float* __restrict__ r, const float* __restrict__ k,
                      const float* __restrict__ u, float* __restrict__ ruk)
{
    const int row = blockIdx.x;
    const int c   = threadIdx.x;            // 0..767
    const int h   = c >> 6;
    const int j   = c & 63;
    size_t idx = (size_t)row * C_ + c;
    float p = r[idx] * u[c] * k[idx];
#pragma unroll
    for (int off = 16; off; off >>= 1) p += __shfl_xor_sync(0xffffffffu, p, off);
    __shared__ float ws[24];
    if ((c & 31) == 0) ws[c >> 5] = p;
    __syncthreads();
    if (j == 0) ruk[(size_t)row * H_ + h] = ws[2 * h] + ws[2 * h + 1];
}

// ==========================================================================
// Kernel: WKV6 recurrence. One block per (b,h); 64 threads (value index i).
// ==========================================================================
__global__ void __launch_bounds__(64)
k_wkv(const float* __restrict__ r, const float* __restrict__ k,
      const float* __restrict__ v, const float* __restrict__ wd,
      const float* __restrict__ ruk, float* __restrict__ y)
{
    const int bh = blockIdx.x;
    const int b  = bh / H_;
    const int h  = bh % H_;
    const int i  = threadIdx.x;

    __shared__ __align__(16) float sr[64];
    __shared__ __align__(16) float sk[64];
    __shared__ __align__(16) float sw[64];

    float S[64];
#pragma unroll
    for (int j = 0; j < 64; j++) S[j] = 0.f;

    const size_t base  = (size_t)b * T_ * C_ + h * 64;
    const size_t rbase = (size_t)b * T_ * H_ + h;

    for (int t = 0; t < T_; t++) {
        size_t idx = base + (size_t)t * C_ + i;
        sr[i] = r[idx];
        sk[i] = k[idx];
        sw[i] = wd[idx];
        float vi = v[idx];
        __syncthreads();

        float y0 = 0.f, y1 = 0.f, y2 = 0.f, y3 = 0.f;
#pragma unroll
        for (int q = 0; q < 16; q++) {
            float4 r4 = *(const float4*)(sr + 4 * q);
            float4 k4 = *(const float4*)(sk + 4 * q);
            float4 w4 = *(const float4*)(sw + 4 * q);
            float kv;
            kv = k4.x * vi; y0 = fmaf(r4.x, S[4*q+0], y0); S[4*q+0] = fmaf(w4.x, S[4*q+0], kv);
            kv = k4.y * vi; y1 = fmaf(r4.y, S[4*q+1], y1); S[4*q+1] = fmaf(w4.y, S[4*q+1], kv);
            kv = k4.z * vi; y2 = fmaf(r4.z, S[4*q+2], y2); S[4*q+2] = fmaf(w4.z, S[4*q+2], kv);
            kv = k4.w * vi; y3 = fmaf(r4.w, S[4*q+3], y3); S[4*q+3] = fmaf(w4.w, S[4*q+3], kv);
        }
        float yv = (y0 + y1) + (y2 + y3);
        yv = fmaf(ruk[rbase + (size_t)t * H_], vi, yv);
        y[idx] = yv;
        __syncthreads();
    }
}

// ==========================================================================
// Kernel: GroupNorm(12 groups of 64) * g  -> yn
// ==========================================================================
__global__ void k_gnorm(const float* __restrict__ y, const float* __restrict__ gbuf,
                        const float* __restrict__ lnw, const float* __restrict__ lnb,
                        float* __restrict__ out)
{
    const int row = blockIdx.x;
    const int c   = threadIdx.x;             // 0..767
    size_t idx = (size_t)row * C_ + c;
    float v = y[idx];
    float s = v, s2 = v * v;
#pragma unroll
    for (int off = 16; off; off >>= 1) {
        s  += __shfl_xor_sync(0xffffffffu, s,  off);
        s2 += __shfl_xor_sync(0xffffffffu, s2, off);
    }
    __shared__ float as[24], as2[24];
    if ((c & 31) == 0) { as[c >> 5] = s; as2[c >> 5] = s2; }
    __syncthreads();
    const int g = c >> 6;
    float sum  = as[2 * g]  + as[2 * g + 1];
    float sum2 = as2[2 * g] + as2[2 * g + 1];
    float mu   = sum * (1.f / 64.f);
    float var  = sum2 * (1.f / 64.f) - mu * mu;
    float nv   = (v - mu) * rsqrtf(var + 1e-5f);
    out[idx] = fmaf(nv, lnw[c], lnb[c]) * gbuf[idx];
}

// ==========================================================================
// Host launcher
// ==========================================================================
extern "C" void kernel_launch(void* const* d_in, const int* in_sizes, int n_in,
                              void* d_out, int out_size)
{
    const float* x     = (const float*)d_in[0];
    const float* W_r   = (const float*)d_in[1];
    const float* W_k   = (const float*)d_in[2];
    const float* W_v   = (const float*)d_in[3];
    const float* W_g   = (const float*)d_in[4];
    const float* W_o   = (const float*)d_in[5];
    const float* maa_x = (const float*)d_in[6];
    const float* maa_w = (const float*)d_in[7];
    const float* maa_k = (const float*)d_in[8];
    const float* maa_v = (const float*)d_in[9];
    const float* maa_r = (const float*)d_in[10];
    const float* maa_g = (const float*)d_in[11];
    const float* maa_w1= (const float*)d_in[12];
    const float* maa_w2= (const float*)d_in[13];
    const float* tdec  = (const float*)d_in[14];
    const float* dec_w1= (const float*)d_in[15];
    const float* dec_w2= (const float*)d_in[16];
    const float* faaaa = (const float*)d_in[17];
    const float* ln_w  = (const float*)d_in[18];
    const float* ln_b  = (const float*)d_in[19];
    (void)in_sizes; (void)n_in; (void)out_size;

    float* S = nullptr;
    cudaGetSymbolAddress((void**)&S, g_scratch);

    float* xx   = S + OFF_XX;
    float* xxx  = S + OFF_XXX;
    float* t5   = S + OFF_T5;
    float* xw   = S + OFF_XW;
    float* xk   = S + OFF_XK;
    float* xv   = S + OFF_XV;
    float* xr   = S + OFF_XR;
    float* xg   = S + OFF_XG;
    float* rb   = S + OFF_R;
    float* kb   = S + OFF_K;
    float* vb   = S + OFF_V;
    float* gb   = S + OFF_G;
    float* h1   = S + OFF_H1;
    float* wdec = S + OFF_WDEC;
    float* yb   = S + OFF_Y;
    float* yn   = S + OFF_YN;
    float* ruk  = S + OFF_RUK;
    float* outp = (float*)d_out;

    // 1. shift + xxx
    k_shift<<<(unsigned)(NC_ / 256), 256>>>(x, maa_x, xx, xxx);

    // 2. t5 = tanh(xxx @ maa_w1)   [8192,160], NN
    k_gemm<1, false><<<dim3(2, NR_ / 128), 256>>>(xxx, maa_w1, t5, NR_, 160, C_, nullptr);

    // 3. token mix -> xw..xg
    k_mix<<<dim3(NR_ / 32, C_ / 128), 256>>>(x, xx, t5, maa_w2,
                                             maa_w, maa_k, maa_v, maa_r, maa_g,
                                             xw, xk, xv, xr, xg);

    // 4. big NT GEMMs
    dim3 gBig(C_ / 128, NR_ / 128);
    k_gemm<0, true><<<gBig, 256>>>(xr, W_r, rb, NR_, C_, C_, nullptr);
    k_gemm<0, true><<<gBig, 256>>>(xk, W_k, kb, NR_, C_, C_, nullptr);
    k_gemm<0, true><<<gBig, 256>>>(xv, W_v, vb, NR_, C_, C_, nullptr);
    k_gemm<2, true><<<gBig, 256>>>(xg, W_g, gb, NR_, C_, C_, nullptr);   // relu

    // 5. decay path: h1 = tanh(xw @ dec_w1); wdec = exp(-exp(tdec + h1 @ dec_w2))
    k_gemm<1, false><<<dim3(1, NR_ / 128), 256>>>(xw, dec_w1, h1, NR_, 64, C_, nullptr);
    k_gemm<3, false><<<dim3(C_ / 128, NR_ / 128), 256>>>(h1, dec_w2, wdec, NR_, C_, 64, tdec);

    // 6. wkv recurrence
    k_ruk<<<NR_, C_>>>(rb, kb, faaaa, ruk);
    k_wkv<<<B_ * H_, 64>>>(rb, kb, vb, wdec, ruk, yb);

    // 7. groupnorm * g
    k_gnorm<<<NR_, C_>>>(yb, gb, ln_w, ln_b, yn);

    // 8. out = yn @ W_o^T
    k_gemm<0, true><<<gBig, 256>>>(yn, W_o, outp, NR_, C_, C_, nullptr);
}

// round 3
// speedup vs baseline: 1.0649x; 1.0649x over previous
#include <cuda_runtime.h>
#include <math.h>
#include <stdint.h>

// ---------------- problem constants (fixed shapes) ----------------
#define B_   8
#define T_   1024
#define C_   768
#define H_   12
#define HS_  64
#define PH_  32
#define PW_  32
#define NR_  (B_ * T_)          // 8192 rows
#define NC_  ((size_t)NR_ * C_) // 6291456 elems

// ---------------- scratch layout ----------------
__device__ __align__(16) float g_scratch[14 * NC_ + (size_t)NR_ * 160 + (size_t)NR_ * 64 + (size_t)NR_ * H_];

#define OFF_XX   ((size_t)0)
#define OFF_XXX  (OFF_XX  + NC_)
#define OFF_T5   (OFF_XXX + NC_)
#define OFF_XW   (OFF_T5  + (size_t)NR_ * 160)
#define OFF_XK   (OFF_XW  + NC_)
#define OFF_XV   (OFF_XK  + NC_)
#define OFF_XR   (OFF_XV  + NC_)
#define OFF_XG   (OFF_XR  + NC_)
#define OFF_R    (OFF_XG  + NC_)
#define OFF_K    (OFF_R   + NC_)
#define OFF_V    (OFF_K   + NC_)
#define OFF_G    (OFF_V   + NC_)
#define OFF_H1   (OFF_G   + NC_)
#define OFF_WDEC (OFF_H1  + (size_t)NR_ * 64)
#define OFF_Y    (OFF_WDEC+ NC_)
#define OFF_YN   (OFF_Y   + NC_)
#define OFF_RUK  (OFF_YN  + NC_)

// ==========================================================================
// Kernel 1: q-shift  ->  xx = shift(x) - x ;  xxx = x + xx * maa_x
// ==========================================================================
__global__ void k_shift(const float* __restrict__ x, const float* __restrict__ maa_x,
                        float* __restrict__ xx, float* __restrict__ xxx)
{
    int idx = blockIdx.x * blockDim.x + threadIdx.x;
    int c  = idx % C_;
    int bt = idx / C_;
    int t  = bt % T_;
    int w  = t % PW_;
    int h  = t / PW_;
    int quarter = (c & (HS_ - 1)) >> 4;

    float src = 0.f;
    if (quarter == 0)      { if (w > 0)       src = x[idx - C_]; }
    else if (quarter == 1) { if (w < PW_ - 1) src = x[idx + C_]; }
    else if (quarter == 2) { if (h > 0)       src = x[idx - PW_ * C_]; }
    else                   { if (h < PH_ - 1) src = x[idx + PW_ * C_]; }

    float xv = x[idx];
    float d  = src - xv;
    xx[idx]  = d;
    xxx[idx] = fmaf(d, maa_x[c], xv);
}

// ==========================================================================
// Pipelined tiled fp32 GEMM:  C[M,N] = epi( A[M,K] @ B )
//   BNT = true : B stored [N,K] row-major (A @ B^T)
//   BNT = false: B stored [K,N] row-major (A @ B)
// EPI: 0 none, 1 tanh, 2 relu, 3 exp(-exp(bias[n] + v))
// 128x128 tile, BK=16, 256 thr, 8x8 micro, double-buffered smem,
// global loads for tile k+1 issued before compute of tile k. 1 bar/iter.
// Warp layout: 8 warps as 2x4 (64x32 warp tiles); lanes as 8x4.
// ==========================================================================
template<int EPI, bool BNT>
__global__ void __launch_bounds__(256, 2)
k_gemm(const float* __restrict__ A, const float* __restrict__ B,
       float* __restrict__ Cmat, int M, int N, int K, const float* __restrict__ bias)
{
    __shared__ float As[2][16][132];
    __shared__ float Bs[2][16][132];

    const int m0   = blockIdx.y * 128;
    const int n0   = blockIdx.x * 128;
    const int tid  = threadIdx.x;
    const int warp = tid >> 5;
    const int lane = tid & 31;
    const int tm   = (warp >> 2) * 64 + (lane >> 2) * 8;  // 0..120
    const int tn   = (warp & 3) * 32 + (lane & 3) * 8;    // 0..120

    float acc[8][8];
#pragma unroll
    for (int i = 0; i < 8; i++)
#pragma unroll
        for (int j = 0; j < 8; j++) acc[i][j] = 0.f;

    float4 aR[2], bR[2];

    // ---------------- global-load helpers (element id e = tid + l*256) -----
    // A: am = e>>2 (0..127), ak = (e&3)*4
    // B (BNT, [N,K]):  bn = e>>2, bk = (e&3)*4
    // B (NN,  [K,N]):  bk = e>>5 (0..15), bn = (e&31)*4
#define LDG_TILE(k0_)                                                          \
    {                                                                          \
        _Pragma("unroll")                                                      \
        for (int l = 0; l < 2; l++) {                                          \
            int e  = tid + l * 256;                                            \
            int am = e >> 2;                                                   \
            int ak = (e & 3) * 4;                                              \
            aR[l] = *(const float4*)(A + (size_t)(m0 + am) * K + (k0_) + ak);  \
            if (BNT) {                                                         \
                int bn = e >> 2;                                               \
                int bk = (e & 3) * 4;                                          \
                bR[l] = make_float4(0.f, 0.f, 0.f, 0.f);                       \
                if (n0 + bn < N)                                               \
                    bR[l] = *(const float4*)(B + (size_t)(n0 + bn) * K + (k0_) + bk); \
            } else {                                                           \
                int bk = e >> 5;                                               \
                int bn = (e & 31) * 4;                                         \
                bR[l] = make_float4(0.f, 0.f, 0.f, 0.f);                       \
                if (n0 + bn < N)                                               \
                    bR[l] = *(const float4*)(B + (size_t)((k0_) + bk) * N + n0 + bn); \
            }                                                                  \
        }                                                                      \
    }

#define STS_TILE(buf_)                                                         \
    {                                                                          \
        _Pragma("unroll")                                                      \
        for (int l = 0; l < 2; l++) {                                          \
            int e  = tid + l * 256;                                            \
            int am = e >> 2;                                                   \
            int ak = (e & 3) * 4;                                              \
            As[buf_][ak + 0][am] = aR[l].x; As[buf_][ak + 1][am] = aR[l].y;    \
            As[buf_][ak + 2][am] = aR[l].z; As[buf_][ak + 3][am] = aR[l].w;    \
            if (BNT) {                                                         \
                int bn = e >> 2;                                               \
                int bk = (e & 3) * 4;                                          \
                Bs[buf_][bk + 0][bn] = bR[l].x; Bs[buf_][bk + 1][bn] = bR[l].y;\
                Bs[buf_][bk + 2][bn] = bR[l].z; Bs[buf_][bk + 3][bn] = bR[l].w;\
            } else {                                                           \
                int bk = e >> 5;                                               \
                int bn = (e & 31) * 4;                                         \
                *(float4*)(&Bs[buf_][bk][bn]) = bR[l];                         \
            }                                                                  \
        }                                                                      \
    }

    // prologue: tile 0
    LDG_TILE(0);
    STS_TILE(0);
    __syncthreads();

    int buf = 0;
    for (int k0 = 0; k0 < K; k0 += 16) {
        const bool hasNext = (k0 + 16 < K);
        if (hasNext) LDG_TILE(k0 + 16);

#pragma unroll
        for (int kk = 0; kk < 16; kk++) {
            float a[8], b[8];
            *(float4*)(a)     = *(const float4*)(&As[buf][kk][tm]);
            *(float4*)(a + 4) = *(const float4*)(&As[buf][kk][tm + 4]);
            *(float4*)(b)     = *(const float4*)(&Bs[buf][kk][tn]);
            *(float4*)(b + 4) = *(const float4*)(&Bs[buf][kk][tn + 4]);
#pragma unroll
            for (int i = 0; i < 8; i++)
#pragma unroll
                for (int j = 0; j < 8; j++)
                    acc[i][j] = fmaf(a[i], b[j], acc[i][j]);
        }

        if (hasNext) {
            STS_TILE(buf ^ 1);
            __syncthreads();
            buf ^= 1;
        }
    }
#undef LDG_TILE
#undef STS_TILE

    // ---- epilogue + store ----
#pragma unroll
    for (int i = 0; i < 8; i++) {
        int m = m0 + tm + i;
#pragma unroll
        for (int j = 0; j < 8; j++) {
            int n = n0 + tn + j;
            if (n < N) {
                float v = acc[i][j];
                if (EPI == 1) v = tanhf(v);
                else if (EPI == 2) v = fmaxf(v, 0.f);
                else if (EPI == 3) v = expf(-expf(bias[n] + v));
                Cmat[(size_t)m * N + n] = v;
            }
        }
    }
}

// ==========================================================================
// Kernel 3: token-mix  x{w,k,v,r,g} = x + xx*(maa_f + (t5 @ maa_w2[f]))
// ==========================================================================
__global__ void __launch_bounds__(256)
k_mix(const float* __restrict__ x, const float* __restrict__ xx,
      const float* __restrict__ t5, const float* __restrict__ w2,
      const float* __restrict__ ma0, const float* __restrict__ ma1,
      const float* __restrict__ ma2, const float* __restrict__ ma3,
      const float* __restrict__ ma4,
      float* __restrict__ o0, float* __restrict__ o1, float* __restrict__ o2,
      float* __restrict__ o3, float* __restrict__ o4)
{
    const int r0  = blockIdx.x * 32;
    const int c0  = blockIdx.y * 128;
    const int tid = threadIdx.x;
    const int cl  = tid & 127;
    const int rh  = tid >> 7;

    __shared__ __align__(16) float tsh[32][36];
    __shared__ float wsh[32][128];

    const float* maas[5] = { ma0, ma1, ma2, ma3, ma4 };
    float*       outs[5] = { o0, o1, o2, o3, o4 };

    float xr_[16], xxr_[16];
#pragma unroll
    for (int kk = 0; kk < 16; kk++) {
        size_t idx = (size_t)(r0 + rh + 2 * kk) * C_ + c0 + cl;
        xr_[kk]  = x[idx];
        xxr_[kk] = xx[idx];
    }

#pragma unroll
    for (int f = 0; f < 5; f++) {
#pragma unroll
        for (int l = 0; l < 4; l++) {
            int e = tid + l * 256;
            tsh[e >> 5][e & 31] = t5[(size_t)(r0 + (e >> 5)) * 160 + f * 32 + (e & 31)];
        }
#pragma unroll
        for (int l = 0; l < 16; l++) {
            int e = tid + l * 256;
            wsh[e >> 7][e & 127] = w2[(size_t)(f * 32 + (e >> 7)) * C_ + c0 + (e & 127)];
        }
        __syncthreads();

        float wreg[32];
#pragma unroll
        for (int rr = 0; rr < 32; rr++) wreg[rr] = wsh[rr][cl];

        const float mf = maas[f][c0 + cl];
        float* const outp = outs[f];
#pragma unroll
        for (int kk = 0; kk < 16; kk++) {
            const int row = rh + 2 * kk;
            const float4* trow = (const float4*)(&tsh[row][0]);
            float a = 0.f;
#pragma unroll
            for (int q = 0; q < 8; q++) {
                float4 t4 = trow[q];
                a = fmaf(t4.x, wreg[4 * q + 0], a);
                a = fmaf(t4.y, wreg[4 * q + 1], a);
                a = fmaf(t4.z, wreg[4 * q + 2], a);
                a = fmaf(t4.w, wreg[4 * q + 3], a);
            }
            size_t idx = (size_t)(r0 + row) * C_ + c0 + cl;
            outp[idx] = fmaf(xxr_[kk], mf + a, xr_[kk]);
        }
        __syncthreads();
    }
}

// ==========================================================================
// Kernel: ruk[row,h] = sum_j r[row, h*64+j] * u[h*64+j] * k[row, h*64+j]
// ==========================================================================
__global__ void k_ruk(const float* __restrict__ r, const float* __restrict__ k,
                      const float* __restrict__ u, float* __restrict__ ruk)
{
    const int row = blockIdx.x;
    const int c   = threadIdx.x;
    const int h   = c >> 6;
    const int j   = c & 63;
    size_t idx = (size_t)row * C_ + c;
    float p = r[idx] * u[c] * k[idx];
#pragma unroll
    for (int off = 16; off; off >>= 1) p += __shfl_xor_sync(0xffffffffu, p, off);
    __shared__ float ws[24];
    if ((c & 31) == 0) ws[c >> 5] = p;
    __syncthreads();
    if (j == 0) ruk[(size_t)row * H_ + h] = ws[2 * h] + ws[2 * h + 1];
}

// ==========================================================================
// Kernel: WKV6 recurrence. One block per (b,h); 256 threads.
//   i = tid & 63 (value idx), q = tid >> 6 (j-quarter, 16 j's each).
//   S[16] regs/thread; partial y reduced through smem; next-t prefetch.
// ==========================================================================
__global__ void __launch_bounds__(256)
k_wkv(const float* __restrict__ r, const float* __restrict__ k,
      const float* __restrict__ v, const float* __restrict__ wd,
      const float* __restrict__ ruk, float* __restrict__ y)
{
    const int bh = blockIdx.x;
    const int b  = bh / H_;
    const int h  = bh % H_;
    const int tid = threadIdx.x;
    const int i  = tid & 63;
    const int q  = tid >> 6;

    __shared__ __align__(16) float sr[64];
    __shared__ __align__(16) float sk[64];
    __shared__ __align__(16) float sw[64];
    __shared__ __align__(16) float sv[64];
    __shared__ float part[3][64];

    float S[16];
#pragma unroll
    for (int jj = 0; jj < 16; jj++) S[jj] = 0.f;

    const size_t base  = (size_t)b * T_ * C_ + h * 64;
    const size_t rbase = (size_t)b * T_ * H_ + h;

    // quarter q streams one of the four input arrays at column i
    const float* mysrc = (q == 0) ? r : (q == 1) ? k : (q == 2) ? wd : v;

    float cur = mysrc[base + i];

    for (int t = 0; t < T_; t++) {
        if (q == 0)      sr[i] = cur;
        else if (q == 1) sk[i] = cur;
        else if (q == 2) sw[i] = cur;
        else             sv[i] = cur;
        __syncthreads();

        float nxt = cur;
        if (t + 1 < T_) nxt = mysrc[base + (size_t)(t + 1) * C_ + i];  // prefetch

        const float vi = sv[i];
        float yp = 0.f;
#pragma unroll
        for (int g4 = 0; g4 < 4; g4++) {
            float4 r4 = *(const float4*)(sr + q * 16 + g4 * 4);
            float4 k4 = *(const float4*)(sk + q * 16 + g4 * 4);
            float4 w4 = *(const float4*)(sw + q * 16 + g4 * 4);
            float kv;
            kv = k4.x * vi; yp = fmaf(r4.x, S[4*g4+0], yp); S[4*g4+0] = fmaf(w4.x, S[4*g4+0], kv);
            kv = k4.y * vi; yp = fmaf(r4.y, S[4*g4+1], yp); S[4*g4+1] = fmaf(w4.y, S[4*g4+1], kv);
            kv = k4.z * vi; yp = fmaf(r4.z, S[4*g4+2], yp); S[4*g4+2] = fmaf(w4.z, S[4*g4+2], kv);
            kv = k4.w * vi; yp = fmaf(r4.w, S[4*g4+3], yp); S[4*g4+3] = fmaf(w4.w, S[4*g4+3], kv);
        }
        if (q) part[q - 1][i] = yp;
        __syncthreads();

        if (q == 0) {
            float yv = yp + part[0][i] + part[1][i] + part[2][i];
            yv = fmaf(ruk[rbase + (size_t)t * H_], vi, yv);
            y[base + (size_t)t * C_ + i] = yv;
        }
        cur = nxt;
    }
}

// ==========================================================================
// Kernel: GroupNorm(12 groups of 64) * g  -> yn
// ==========================================================================
__global__ void k_gnorm(const float* __restrict__ y, const float* __restrict__ gbuf,
                        const float* __restrict__ lnw, const float* __restrict__ lnb,
                        float* __restrict__ out)
{
    const int row = blockIdx.x;
    const int c   = threadIdx.x;
    size_t idx = (size_t)row * C_ + c;
    float v = y[idx];
    float s = v, s2 = v * v;
#pragma unroll
    for (int off = 16; off; off >>= 1) {
        s  += __shfl_xor_sync(0xffffffffu, s,  off);
        s2 += __shfl_xor_sync(0xffffffffu, s2, off);
    }
    __shared__ float as[24], as2[24];
    if ((c & 31) == 0) { as[c >> 5] = s; as2[c >> 5] = s2; }
    __syncthreads();
    const int g = c >> 6;
    float sum  = as[2 * g]  + as[2 * g + 1];
    float sum2 = as2[2 * g] + as2[2 * g + 1];
    float mu   = sum * (1.f / 64.f);
    float var  = sum2 * (1.f / 64.f) - mu * mu;
    float nv   = (v - mu) * rsqrtf(var + 1e-5f);
    out[idx] = fmaf(nv, lnw[c], lnb[c]) * gbuf[idx];
}

// ==========================================================================
// Host launcher
// ==========================================================================
extern "C" void kernel_launch(void* const* d_in, const int* in_sizes, int n_in,
                              void* d_out, int out_size)
{
    const float* x     = (const float*)d_in[0];
    const float* W_r   = (const float*)d_in[1];
    const float* W_k   = (const float*)d_in[2];
    const float* W_v   = (const float*)d_in[3];
    const float* W_g   = (const float*)d_in[4];
    const float* W_o   = (const float*)d_in[5];
    const float* maa_x = (const float*)d_in[6];
    const float* maa_w = (const float*)d_in[7];
    const float* maa_k = (const float*)d_in[8];
    const float* maa_v = (const float*)d_in[9];
    const float* maa_r = (const float*)d_in[10];
    const float* maa_g = (const float*)d_in[11];
    const float* maa_w1= (const float*)d_in[12];
    const float* maa_w2= (const float*)d_in[13];
    const float* tdec  = (const float*)d_in[14];
    const float* dec_w1= (const float*)d_in[15];
    const float* dec_w2= (const float*)d_in[16];
    const float* faaaa = (const float*)d_in[17];
    const float* ln_w  = (const float*)d_in[18];
    const float* ln_b  = (const float*)d_in[19];
    (void)in_sizes; (void)n_in; (void)out_size;

    float* S = nullptr;
    cudaGetSymbolAddress((void**)&S, g_scratch);

    float* xx   = S + OFF_XX;
    float* xxx  = S + OFF_XXX;
    float* t5   = S + OFF_T5;
    float* xw   = S + OFF_XW;
    float* xk   = S + OFF_XK;
    float* xv   = S + OFF_XV;
    float* xr   = S + OFF_XR;
    float* xg   = S + OFF_XG;
    float* rb   = S + OFF_R;
    float* kb   = S + OFF_K;
    float* vb   = S + OFF_V;
    float* gb   = S + OFF_G;
    float* h1   = S + OFF_H1;
    float* wdec = S + OFF_WDEC;
    float* yb   = S + OFF_Y;
    float* yn   = S + OFF_YN;
    float* ruk  = S + OFF_RUK;
    float* outp = (float*)d_out;

    // 1. shift + xxx
    k_shift<<<(unsigned)(NC_ / 256), 256>>>(x, maa_x, xx, xxx);

    // 2. t5 = tanh(xxx @ maa_w1)   [8192,160], NN
    k_gemm<1, false><<<dim3(2, NR_ / 128), 256>>>(xxx, maa_w1, t5, NR_, 160, C_, nullptr);

    // 3. token mix -> xw..xg
    k_mix<<<dim3(NR_ / 32, C_ / 128), 256>>>(x, xx, t5, maa_w2,
                                             maa_w, maa_k, maa_v, maa_r, maa_g,
                                             xw, xk, xv, xr, xg);

    // 4. big NT GEMMs
    dim3 gBig(C_ / 128, NR_ / 128);
    k_gemm<0, true><<<gBig, 256>>>(xr, W_r, rb, NR_, C_, C_, nullptr);
    k_gemm<0, true><<<gBig, 256>>>(xk, W_k, kb, NR_, C_, C_, nullptr);
    k_gemm<0, true><<<gBig, 256>>>(xv, W_v, vb, NR_, C_, C_, nullptr);
    k_gemm<2, true><<<gBig, 256>>>(xg, W_g, gb, NR_, C_, C_, nullptr);   // relu

    // 5. decay path: h1 = tanh(xw @ dec_w1); wdec = exp(-exp(tdec + h1 @ dec_w2))
    k_gemm<1, false><<<dim3(1, NR_ / 128), 256>>>(xw, dec_w1, h1, NR_, 64, C_, nullptr);
    k_gemm<3, false><<<dim3(C_ / 128, NR_ / 128), 256>>>(h1, dec_w2, wdec, NR_, C_, 64, tdec);

    // 6. wkv recurrence
    k_ruk<<<NR_, C_>>>(rb, kb, faaaa, ruk);
    k_wkv<<<B_ * H_, 256>>>(rb, kb, vb, wdec, ruk, yb);

    // 7. groupnorm * g
    k_gnorm<<<NR_, C_>>>(yb, gb, ln_w, ln_b, yn);

    // 8. out = yn @ W_o^T
    k_gemm<0, true><<<gBig, 256>>>(yn, W_o, outp, NR_, C_, C_, nullptr);
}

// round 5
// speedup vs baseline: 1.4093x; 1.3234x over previous
#include <cuda_runtime.h>
#include <cuda_bf16.h>
#include <math.h>
#include <stdint.h>

// ---------------- problem constants (fixed shapes) ----------------
#define B_   8
#define T_   1024
#define C_   768
#define H_   12
#define HS_  64
#define PH_  32
#define PW_  32
#define NR_  (B_ * T_)          // 8192 rows
#define NC_  ((size_t)NR_ * C_) // 6291456 elems

// ---------------- scratch layout ----------------
__device__ __align__(16) float g_scratch[14 * NC_ + (size_t)NR_ * 160 + (size_t)NR_ * 64 + (size_t)NR_ * H_];
__device__ __align__(16) __nv_bfloat16 g_ahi[NC_];
__device__ __align__(16) __nv_bfloat16 g_alo[NC_];
__device__ __align__(16) __nv_bfloat16 g_whi[(size_t)C_ * C_];
__device__ __align__(16) __nv_bfloat16 g_wlo[(size_t)C_ * C_];

#define OFF_XX   ((size_t)0)
#define OFF_XXX  (OFF_XX  + NC_)
#define OFF_T5   (OFF_XXX + NC_)
#define OFF_XW   (OFF_T5  + (size_t)NR_ * 160)
#define OFF_XK   (OFF_XW  + NC_)
#define OFF_XV   (OFF_XK  + NC_)
#define OFF_XR   (OFF_XV  + NC_)
#define OFF_XG   (OFF_XR  + NC_)
#define OFF_R    (OFF_XG  + NC_)
#define OFF_K    (OFF_R   + NC_)
#define OFF_V    (OFF_K   + NC_)
#define OFF_G    (OFF_V   + NC_)
#define OFF_H1   (OFF_G   + NC_)
#define OFF_WDEC (OFF_H1  + (size_t)NR_ * 64)
#define OFF_Y    (OFF_WDEC+ NC_)
#define OFF_YN   (OFF_Y   + NC_)
#define OFF_RUK  (OFF_YN  + NC_)

// ==========================================================================
// fp32 -> (bf16 hi, bf16 lo) split
// ==========================================================================
__global__ void k_split(const float* __restrict__ in, __nv_bfloat16* __restrict__ hi,
                        __nv_bfloat16* __restrict__ lo, int n)
{
    int i = blockIdx.x * blockDim.x + threadIdx.x;
    if (i >= n) return;
    float a = in[i];
    __nv_bfloat16 h = __float2bfloat16(a);
    hi[i] = h;
    lo[i] = __float2bfloat16(a - __bfloat162float(h));
}

// ==========================================================================
// bf16-split tensor-core GEMM via mma.sync (baseline PTX, works on compute_103):
//   C[8192,768] = epi( A[8192,768] @ W[768,768]^T )
//   D = Ahi*Whi + Alo*Whi + Ahi*Wlo  (virtual K' = 2304 = 72 tiles of K32)
// Block 128x128, 256 thr (8 warps as 2x4, warp tile 64x32), double-buffered.
// Smem layout: per tile, A and B each stored as 4 "16B-chunk planes" of
// 128 rows x 16B, plane stride 2080B -> STS and ldmatrix conflict-free.
// ==========================================================================
#define PLANE_   2080
#define ATILE_   (4 * PLANE_)           // 8320
#define BUFSZ_   (2 * ATILE_)           // 16640 (A planes then B planes)

__device__ __forceinline__ void ldsm_x4(uint32_t* r, uint32_t addr) {
    asm volatile("ldmatrix.sync.aligned.m8n8.x4.shared.b16 {%0,%1,%2,%3}, [%4];"
                 : "=r"(r[0]), "=r"(r[1]), "=r"(r[2]), "=r"(r[3]) : "r"(addr));
}
__device__ __forceinline__ void mma_bf16(float* c, const uint32_t* a, uint32_t b0, uint32_t b1) {
    asm volatile("mma.sync.aligned.m16n8k16.row.col.f32.bf16.bf16.f32 "
                 "{%0,%1,%2,%3}, {%4,%5,%6,%7}, {%8,%9}, {%0,%1,%2,%3};"
                 : "+f"(c[0]), "+f"(c[1]), "+f"(c[2]), "+f"(c[3])
                 : "r"(a[0]), "r"(a[1]), "r"(a[2]), "r"(a[3]), "r"(b0), "r"(b1));
}
__device__ __forceinline__ uint32_t smem_u32(const void* p) {
    uint32_t a;
    asm("{ .reg .u64 t; cvta.to.shared.u64 t, %1; cvt.u32.u64 %0, t; }" : "=r"(a) : "l"(p));
    return a;
}

__global__ void __launch_bounds__(256, 2)
k_gemm_mma(const __nv_bfloat16* __restrict__ Ahi, const __nv_bfloat16* __restrict__ Alo,
           const __nv_bfloat16* __restrict__ Whi, const __nv_bfloat16* __restrict__ Wlo,
           float* __restrict__ Cmat, int doRelu)
{
    __shared__ __align__(16) char sm[2][BUFSZ_];

    const int tid  = threadIdx.x;
    const int warp = tid >> 5;
    const int lane = tid & 31;
    const int m0 = blockIdx.y * 128;
    const int n0 = blockIdx.x * 128;
    const int wm = warp >> 2;      // 0..1  (64 rows)
    const int wn = warp & 3;       // 0..3  (32 cols)

    float acc[4][4][4];            // [mtile16][n8group][4]
#pragma unroll
    for (int i = 0; i < 4; i++)
#pragma unroll
        for (int j = 0; j < 4; j++)
#pragma unroll
            for (int q = 0; q < 4; q++) acc[i][j][q] = 0.f;

    // global->smem mapping: row = tid>>1 (0..127), chunks {0,1} or {2,3}
    const int ldrow = tid >> 1;
    const int ldcb  = (tid & 1) * 2;

    uint4 ra[2], rb[2];

    const uint32_t sb = smem_u32(sm);
    // ldmatrix lane address components
    const int lgrp = lane >> 3;    // 0..3
    const int lrl  = lane & 7;

#define LDG_T(c_)                                                               \
    {                                                                           \
        const int seg_ = (c_) / 24;                                             \
        const int kc_  = ((c_) % 24) * 32;                                      \
        const __nv_bfloat16* Ag = (seg_ == 1) ? Alo : Ahi;                      \
        const __nv_bfloat16* Bg = (seg_ == 2) ? Wlo : Whi;                      \
        const __nv_bfloat16* ap = Ag + (size_t)(m0 + ldrow) * C_ + kc_ + ldcb * 8; \
        const __nv_bfloat16* bp = Bg + (size_t)(n0 + ldrow) * C_ + kc_ + ldcb * 8; \
        ra[0] = *(const uint4*)ap; ra[1] = *(const uint4*)(ap + 8);             \
        rb[0] = *(const uint4*)bp; rb[1] = *(const uint4*)(bp + 8);             \
    }

#define STS_T(buf_)                                                             \
    {                                                                           \
        char* b_ = sm[buf_];                                                    \
        *(uint4*)(b_ + (ldcb + 0) * PLANE_ + ldrow * 16) = ra[0];               \
        *(uint4*)(b_ + (ldcb + 1) * PLANE_ + ldrow * 16) = ra[1];               \
        *(uint4*)(b_ + ATILE_ + (ldcb + 0) * PLANE_ + ldrow * 16) = rb[0];      \
        *(uint4*)(b_ + ATILE_ + (ldcb + 1) * PLANE_ + ldrow * 16) = rb[1];      \
    }

    LDG_T(0);
    STS_T(0);
    __syncthreads();

    for (int c = 0; c < 72; c++) {
        const int buf = c & 1;
        const bool hasNext = (c + 1 < 72);
        if (hasNext) LDG_T(c + 1);

        const uint32_t abase = sb + buf * BUFSZ_;
        const uint32_t bbase = abase + ATILE_;

#pragma unroll
        for (int kk = 0; kk < 2; kk++) {
            uint32_t afr[4][4], bfr[2][4];
#pragma unroll
            for (int mt = 0; mt < 4; mt++) {
                // groups: g0 rows0-7 klo, g1 rows8-15 klo, g2 rows0-7 khi, g3 rows8-15 khi
                int row   = wm * 64 + mt * 16 + (lgrp & 1) * 8 + lrl;
                int chunk = kk * 2 + (lgrp >> 1);
                ldsm_x4(afr[mt], abase + chunk * PLANE_ + row * 16);
            }
#pragma unroll
            for (int nt = 0; nt < 2; nt++) {
                // groups: g0 (n0-7,klo), g1 (n0-7,khi), g2 (n8-15,klo), g3 (n8-15,khi)
                int nr    = wn * 32 + nt * 16 + (lgrp >> 1) * 8 + lrl;
                int chunk = kk * 2 + (lgrp & 1);
                ldsm_x4(bfr[nt], bbase + chunk * PLANE_ + nr * 16);
            }
#pragma unroll
            for (int mt = 0; mt < 4; mt++)
#pragma unroll
                for (int ng = 0; ng < 4; ng++)
                    mma_bf16(acc[mt][ng], afr[mt], bfr[ng >> 1][(ng & 1) * 2 + 0],
                             bfr[ng >> 1][(ng & 1) * 2 + 1]);
        }

        if (hasNext) {
            STS_T(buf ^ 1);
            __syncthreads();
        }
    }
#undef LDG_T
#undef STS_T

    // ---- epilogue ----
#pragma unroll
    for (int mt = 0; mt < 4; mt++) {
        const int r0 = m0 + wm * 64 + mt * 16 + (lane >> 2);
#pragma unroll
        for (int ng = 0; ng < 4; ng++) {
            const int col = n0 + wn * 32 + ng * 8 + (lane & 3) * 2;
            float c0 = acc[mt][ng][0], c1 = acc[mt][ng][1];
            float c2 = acc[mt][ng][2], c3 = acc[mt][ng][3];
            if (doRelu) {
                c0 = fmaxf(c0, 0.f); c1 = fmaxf(c1, 0.f);
                c2 = fmaxf(c2, 0.f); c3 = fmaxf(c3, 0.f);
            }
            *(float2*)(Cmat + (size_t)r0 * C_ + col)       = make_float2(c0, c1);
            *(float2*)(Cmat + (size_t)(r0 + 8) * C_ + col) = make_float2(c2, c3);
        }
    }
}

// ==========================================================================
// Kernel 1: q-shift  ->  xx = shift(x) - x ;  xxx = x + xx * maa_x
// ==========================================================================
__global__ void k_shift(const float* __restrict__ x, const float* __restrict__ maa_x,
                        float* __restrict__ xx, float* __restrict__ xxx)
{
    int idx = blockIdx.x * blockDim.x + threadIdx.x;
    int c  = idx % C_;
    int bt = idx / C_;
    int t  = bt % T_;
    int w  = t % PW_;
    int h  = t / PW_;
    int quarter = (c & (HS_ - 1)) >> 4;

    float src = 0.f;
    if (quarter == 0)      { if (w > 0)       src = x[idx - C_]; }
    else if (quarter == 1) { if (w < PW_ - 1) src = x[idx + C_]; }
    else if (quarter == 2) { if (h > 0)       src = x[idx - PW_ * C_]; }
    else                   { if (h < PH_ - 1) src = x[idx + PW_ * C_]; }

    float xv = x[idx];
    float d  = src - xv;
    xx[idx]  = d;
    xxx[idx] = fmaf(d, maa_x[c], xv);
}

// ==========================================================================
// Pipelined tiled fp32 GEMM (small N/K GEMMs only)
// ==========================================================================
template<int EPI, bool BNT>
__global__ void __launch_bounds__(256, 2)
k_gemm(const float* __restrict__ A, const float* __restrict__ B,
       float* __restrict__ Cmat, int M, int N, int K, const float* __restrict__ bias)
{
    __shared__ float As[2][16][132];
    __shared__ float Bs[2][16][132];

    const int m0   = blockIdx.y * 128;
    const int n0   = blockIdx.x * 128;
    const int tid  = threadIdx.x;
    const int warp = tid >> 5;
    const int lane = tid & 31;
    const int tm   = (warp >> 2) * 64 + (lane >> 2) * 8;
    const int tn   = (warp & 3) * 32 + (lane & 3) * 8;

    float acc[8][8];
#pragma unroll
    for (int i = 0; i < 8; i++)
#pragma unroll
        for (int j = 0; j < 8; j++) acc[i][j] = 0.f;

    float4 aR[2], bR[2];

#define LDG_TILE(k0_)                                                          \
    {                                                                          \
        _Pragma("unroll")                                                      \
        for (int l = 0; l < 2; l++) {                                          \
            int e  = tid + l * 256;                                            \
            int am = e >> 2;                                                   \
            int ak = (e & 3) * 4;                                              \
            aR[l] = *(const float4*)(A + (size_t)(m0 + am) * K + (k0_) + ak);  \
            if (BNT) {                                                         \
                int bn = e >> 2;                                               \
                int bk = (e & 3) * 4;                                          \
                bR[l] = make_float4(0.f, 0.f, 0.f, 0.f);                       \
                if (n0 + bn < N)                                               \
                    bR[l] = *(const float4*)(B + (size_t)(n0 + bn) * K + (k0_) + bk); \
            } else {                                                           \
                int bk = e >> 5;                                               \
                int bn = (e & 31) * 4;                                         \
                bR[l] = make_float4(0.f, 0.f, 0.f, 0.f);                       \
                if (n0 + bn < N)                                               \
                    bR[l] = *(const float4*)(B + (size_t)((k0_) + bk) * N + n0 + bn); \
            }                                                                  \
        }                                                                      \
    }

#define STS_TILE(buf_)                                                         \
    {                                                                          \
        _Pragma("unroll")                                                      \
        for (int l = 0; l < 2; l++) {                                          \
            int e  = tid + l * 256;                                            \
            int am = e >> 2;                                                   \
            int ak = (e & 3) * 4;                                              \
            As[buf_][ak + 0][am] = aR[l].x; As[buf_][ak + 1][am] = aR[l].y;    \
            As[buf_][ak + 2][am] = aR[l].z; As[buf_][ak + 3][am] = aR[l].w;    \
            if (BNT) {                                                         \
                int bn = e >> 2;                                               \
                int bk = (e & 3) * 4;                                          \
                Bs[buf_][bk + 0][bn] = bR[l].x; Bs[buf_][bk + 1][bn] = bR[l].y;\
                Bs[buf_][bk + 2][bn] = bR[l].z; Bs[buf_][bk + 3][bn] = bR[l].w;\
            } else {                                                           \
                int bk = e >> 5;                                               \
                int bn = (e & 31) * 4;                                         \
                *(float4*)(&Bs[buf_][bk][bn]) = bR[l];                         \
            }                                                                  \
        }                                                                      \
    }

    LDG_TILE(0);
    STS_TILE(0);
    __syncthreads();

    int buf = 0;
    for (int k0 = 0; k0 < K; k0 += 16) {
        const bool hasNext = (k0 + 16 < K);
        if (hasNext) LDG_TILE(k0 + 16);

#pragma unroll
        for (int kk = 0; kk < 16; kk++) {
            float a[8], b[8];
            *(float4*)(a)     = *(const float4*)(&As[buf][kk][tm]);
            *(float4*)(a + 4) = *(const float4*)(&As[buf][kk][tm + 4]);
            *(float4*)(b)     = *(const float4*)(&Bs[buf][kk][tn]);
            *(float4*)(b + 4) = *(const float4*)(&Bs[buf][kk][tn + 4]);
#pragma unroll
            for (int i = 0; i < 8; i++)
#pragma unroll
                for (int j = 0; j < 8; j++)
                    acc[i][j] = fmaf(a[i], b[j], acc[i][j]);
        }

        if (hasNext) {
            STS_TILE(buf ^ 1);
            __syncthreads();
            buf ^= 1;
        }
    }
#undef LDG_TILE
#undef STS_TILE

#pragma unroll
    for (int i = 0; i < 8; i++) {
        int m = m0 + tm + i;
#pragma unroll
        for (int j = 0; j < 8; j++) {
            int n = n0 + tn + j;
            if (n < N) {
                float v = acc[i][j];
                if (EPI == 1) v = tanhf(v);
                else if (EPI == 2) v = fmaxf(v, 0.f);
                else if (EPI == 3) v = expf(-expf(bias[n] + v));
                Cmat[(size_t)m * N + n] = v;
            }
        }
    }
}

// ==========================================================================
// Kernel 3: token-mix
// ==========================================================================
__global__ void __launch_bounds__(256)
k_mix(const float* __restrict__ x, const float* __restrict__ xx,
      const float* __restrict__ t5, const float* __restrict__ w2,
      const float* __restrict__ ma0, const float* __restrict__ ma1,
      const float* __restrict__ ma2, const float* __restrict__ ma3,
      const float* __restrict__ ma4,
      float* __restrict__ o0, float* __restrict__ o1, float* __restrict__ o2,
      float* __restrict__ o3, float* __restrict__ o4)
{
    const int r0  = blockIdx.x * 32;
    const int c0  = blockIdx.y * 128;
    const int tid = threadIdx.x;
    const int cl  = tid & 127;
    const int rh  = tid >> 7;

    __shared__ __align__(16) float tsh[32][36];
    __shared__ float wsh[32][128];

    const float* maas[5] = { ma0, ma1, ma2, ma3, ma4 };
    float*       outs[5] = { o0, o1, o2, o3, o4 };

    float xr_[16], xxr_[16];
#pragma unroll
    for (int kk = 0; kk < 16; kk++) {
        size_t idx = (size_t)(r0 + rh + 2 * kk) * C_ + c0 + cl;
        xr_[kk]  = x[idx];
        xxr_[kk] = xx[idx];
    }

#pragma unroll
    for (int f = 0; f < 5; f++) {
#pragma unroll
        for (int l = 0; l < 4; l++) {
            int e = tid + l * 256;
            tsh[e >> 5][e & 31] = t5[(size_t)(r0 + (e >> 5)) * 160 + f * 32 + (e & 31)];
        }
#pragma unroll
        for (int l = 0; l < 16; l++) {
            int e = tid + l * 256;
            wsh[e >> 7][e & 127] = w2[(size_t)(f * 32 + (e >> 7)) * C_ + c0 + (e & 127)];
        }
        __syncthreads();

        float wreg[32];
#pragma unroll
        for (int rr = 0; rr < 32; rr++) wreg[rr] = wsh[rr][cl];

        const float mf = maas[f][c0 + cl];
        float* const outp = outs[f];
#pragma unroll
        for (int kk = 0; kk < 16; kk++) {
            const int row = rh + 2 * kk;
            const float4* trow = (const float4*)(&tsh[row][0]);
            float a = 0.f;
#pragma unroll
            for (int q = 0; q < 8; q++) {
                float4 t4 = trow[q];
                a = fmaf(t4.x, wreg[4 * q + 0], a);
                a = fmaf(t4.y, wreg[4 * q + 1], a);
                a = fmaf(t4.z, wreg[4 * q + 2], a);
                a = fmaf(t4.w, wreg[4 * q + 3], a);
            }
            size_t idx = (size_t)(r0 + row) * C_ + c0 + cl;
            outp[idx] = fmaf(xxr_[kk], mf + a, xr_[kk]);
        }
        __syncthreads();
    }
}

// ==========================================================================
// ruk[row,h] = sum_j r*u*k
// ==========================================================================
__global__ void k_ruk(const float* __restrict__ r, const float* __restrict__ k,
                      const float* __restrict__ u, float* __restrict__ ruk)
{
    const int row = blockIdx.x;
    const int c   = threadIdx.x;
    const int h   = c >> 6;
    const int j   = c & 63;
    size_t idx = (size_t)row * C_ + c;
    float p = r[idx] * u[c] * k[idx];
#pragma unroll
    for (int off = 16; off; off >>= 1) p += __shfl_xor_sync(0xffffffffu, p, off);
    __shared__ float ws[24];
    if ((c & 31) == 0) ws[c >> 5] = p;
    __syncthreads();
    if (j == 0) ruk[(size_t)row * H_ + h] = ws[2 * h] + ws[2 * h + 1];
}

// ==========================================================================
// WKV6 recurrence (256 threads, j split in quarters)
// ==========================================================================
__global__ void __launch_bounds__(256)
k_wkv(const float* __restrict__ r, const float* __restrict__ k,
      const float* __restrict__ v, const float* __restrict__ wd,
      const float* __restrict__ ruk, float* __restrict__ y)
{
    const int bh = blockIdx.x;
    const int b  = bh / H_;
    const int h  = bh % H_;
    const int tid = threadIdx.x;
    const int i  = tid & 63;
    const int q  = tid >> 6;

    __shared__ __align__(16) float sr[64];
    __shared__ __align__(16) float sk[64];
    __shared__ __align__(16) float sw[64];
    __shared__ __align__(16) float sv[64];
    __shared__ float part[3][64];

    float S[16];
#pragma unroll
    for (int jj = 0; jj < 16; jj++) S[jj] = 0.f;

    const size_t base  = (size_t)b * T_ * C_ + h * 64;
    const size_t rbase = (size_t)b * T_ * H_ + h;

    const float* mysrc = (q == 0) ? r : (q == 1) ? k : (q == 2) ? wd : v;
    float cur = mysrc[base + i];

    for (int t = 0; t < T_; t++) {
        if (q == 0)      sr[i] = cur;
        else if (q == 1) sk[i] = cur;
        else if (q == 2) sw[i] = cur;
        else             sv[i] = cur;
        __syncthreads();

        float nxt = cur;
        if (t + 1 < T_) nxt = mysrc[base + (size_t)(t + 1) * C_ + i];

        const float vi = sv[i];
        float yp = 0.f;
#pragma unroll
        for (int g4 = 0; g4 < 4; g4++) {
            float4 r4 = *(const float4*)(sr + q * 16 + g4 * 4);
            float4 k4 = *(const float4*)(sk + q * 16 + g4 * 4);
            float4 w4 = *(const float4*)(sw + q * 16 + g4 * 4);
            float kv;
            kv = k4.x * vi; yp = fmaf(r4.x, S[4*g4+0], yp); S[4*g4+0] = fmaf(w4.x, S[4*g4+0], kv);
            kv = k4.y * vi; yp = fmaf(r4.y, S[4*g4+1], yp); S[4*g4+1] = fmaf(w4.y, S[4*g4+1], kv);
            kv = k4.z * vi; yp = fmaf(r4.z, S[4*g4+2], yp); S[4*g4+2] = fmaf(w4.z, S[4*g4+2], kv);
            kv = k4.w * vi; yp = fmaf(r4.w, S[4*g4+3], yp); S[4*g4+3] = fmaf(w4.w, S[4*g4+3], kv);
        }
        if (q) part[q - 1][i] = yp;
        __syncthreads();

        if (q == 0) {
            float yv = yp + part[0][i] + part[1][i] + part[2][i];
            yv = fmaf(ruk[rbase + (size_t)t * H_], vi, yv);
            y[base + (size_t)t * C_ + i] = yv;
        }
        cur = nxt;
    }
}

// ==========================================================================
// GroupNorm * g
// ==========================================================================
__global__ void k_gnorm(const float* __restrict__ y, const float* __restrict__ gbuf,
                        const float* __restrict__ lnw, const float* __restrict__ lnb,
                        float* __restrict__ out)
{
    const int row = blockIdx.x;
    const int c   = threadIdx.x;
    size_t idx = (size_t)row * C_ + c;
    float v = y[idx];
    float s = v, s2 = v * v;
#pragma unroll
    for (int off = 16; off; off >>= 1) {
        s  += __shfl_xor_sync(0xffffffffu, s,  off);
        s2 += __shfl_xor_sync(0xffffffffu, s2, off);
    }
    __shared__ float as[24], as2[24];
    if ((c & 31) == 0) { as[c >> 5] = s; as2[c >> 5] = s2; }
    __syncthreads();
    const int g = c >> 6;
    float sum  = as[2 * g]  + as[2 * g + 1];
    float sum2 = as2[2 * g] + as2[2 * g + 1];
    float mu   = sum * (1.f / 64.f);
    float var  = sum2 * (1.f / 64.f) - mu * mu;
    float nv   = (v - mu) * rsqrtf(var + 1e-5f);
    out[idx] = fmaf(nv, lnw[c], lnb[c]) * gbuf[idx];
}

// ==========================================================================
// Host launcher
// ==========================================================================
extern "C" void kernel_launch(void* const* d_in, const int* in_sizes, int n_in,
                              void* d_out, int out_size)
{
    const float* x     = (const float*)d_in[0];
    const float* W_r   = (const float*)d_in[1];
    const float* W_k   = (const float*)d_in[2];
    const float* W_v   = (const float*)d_in[3];
    const float* W_g   = (const float*)d_in[4];
    const float* W_o   = (const float*)d_in[5];
    const float* maa_x = (const float*)d_in[6];
    const float* maa_w = (const float*)d_in[7];
    const float* maa_k = (const float*)d_in[8];
    const float* maa_v = (const float*)d_in[9];
    const float* maa_r = (const float*)d_in[10];
    const float* maa_g = (const float*)d_in[11];
    const float* maa_w1= (const float*)d_in[12];
    const float* maa_w2= (const float*)d_in[13];
    const float* tdec  = (const float*)d_in[14];
    const float* dec_w1= (const float*)d_in[15];
    const float* dec_w2= (const float*)d_in[16];
    const float* faaaa = (const float*)d_in[17];
    const float* ln_w  = (const float*)d_in[18];
    const float* ln_b  = (const float*)d_in[19];
    (void)in_sizes; (void)n_in; (void)out_size;

    float* S = nullptr;
    cudaGetSymbolAddress((void**)&S, g_scratch);
    __nv_bfloat16 *ahi = nullptr, *alo = nullptr, *whi = nullptr, *wlo = nullptr;
    cudaGetSymbolAddress((void**)&ahi, g_ahi);
    cudaGetSymbolAddress((void**)&alo, g_alo);
    cudaGetSymbolAddress((void**)&whi, g_whi);
    cudaGetSymbolAddress((void**)&wlo, g_wlo);

    float* xx   = S + OFF_XX;
    float* xxx  = S + OFF_XXX;
    float* t5   = S + OFF_T5;
    float* xw   = S + OFF_XW;
    float* xk   = S + OFF_XK;
    float* xv   = S + OFF_XV;
    float* xr   = S + OFF_XR;
    float* xg   = S + OFF_XG;
    float* rb   = S + OFF_R;
    float* kb   = S + OFF_K;
    float* vb   = S + OFF_V;
    float* gb   = S + OFF_G;
    float* h1   = S + OFF_H1;
    float* wdec = S + OFF_WDEC;
    float* yb   = S + OFF_Y;
    float* yn   = S + OFF_YN;
    float* ruk  = S + OFF_RUK;
    float* outp = (float*)d_out;

    const int nAct = (int)NC_;
    const int nW   = C_ * C_;
    const dim3 gTC(C_ / 128, NR_ / 128);   // (6, 64)

    // 1. shift + xxx
    k_shift<<<(unsigned)(NC_ / 256), 256>>>(x, maa_x, xx, xxx);

    // 2. t5 = tanh(xxx @ maa_w1)
    k_gemm<1, false><<<dim3(2, NR_ / 128), 256>>>(xxx, maa_w1, t5, NR_, 160, C_, nullptr);

    // 3. token mix -> xw..xg
    k_mix<<<dim3(NR_ / 32, C_ / 128), 256>>>(x, xx, t5, maa_w2,
                                             maa_w, maa_k, maa_v, maa_r, maa_g,
                                             xw, xk, xv, xr, xg);

    // 4. big NT GEMMs via mma.sync bf16-split
    k_split<<<nAct / 256, 256>>>(xr, ahi, alo, nAct);
    k_split<<<nW / 256, 256>>>(W_r, whi, wlo, nW);
    k_gemm_mma<<<gTC, 256>>>(ahi, alo, whi, wlo, rb, 0);

    k_split<<<nAct / 256, 256>>>(xk, ahi, alo, nAct);
    k_split<<<nW / 256, 256>>>(W_k, whi, wlo, nW);
    k_gemm_mma<<<gTC, 256>>>(ahi, alo, whi, wlo, kb, 0);

    k_split<<<nAct / 256, 256>>>(xv, ahi, alo, nAct);
    k_split<<<nW / 256, 256>>>(W_v, whi, wlo, nW);
    k_gemm_mma<<<gTC, 256>>>(ahi, alo, whi, wlo, vb, 0);

    k_split<<<nAct / 256, 256>>>(xg, ahi, alo, nAct);
    k_split<<<nW / 256, 256>>>(W_g, whi, wlo, nW);
    k_gemm_mma<<<gTC, 256>>>(ahi, alo, whi, wlo, gb, 1);   // relu

    // 5. decay path (small fp32 GEMMs)
    k_gemm<1, false><<<dim3(1, NR_ / 128), 256>>>(xw, dec_w1, h1, NR_, 64, C_, nullptr);
    k_gemm<3, false><<<dim3(C_ / 128, NR_ / 128), 256>>>(h1, dec_w2, wdec, NR_, C_, 64, tdec);

    // 6. wkv recurrence
    k_ruk<<<NR_, C_>>>(rb, kb, faaaa, ruk);
    k_wkv<<<B_ * H_, 256>>>(rb, kb, vb, wdec, ruk, yb);

    // 7. groupnorm * g
    k_gnorm<<<NR_, C_>>>(yb, gb, ln_w, ln_b, yn);

    // 8. out = yn @ W_o^T  (mma.sync)
    k_split<<<nAct / 256, 256>>>(yn, ahi, alo, nAct);
    k_split<<<nW / 256, 256>>>(W_o, whi, wlo, nW);
    k_gemm_mma<<<gTC, 256>>>(ahi, alo, whi, wlo, outp, 0);
}